// round 8
// baseline (speedup 1.0000x reference)
#include <cuda_runtime.h>
#include <cstdint>

#define BB   32
#define NN   512
#define DD   256
#define HH   8
#define HDIM 32
#define EE   16384
#define ETOT (EE + NN)

// ---------------- scratch (static device globals; no allocation) -------------
__device__ float    g_xwq[BB * NN * DD];
__device__ float    g_xwk[BB * NN * DD];
__device__ float    g_xwv[BB * NN * DD];
__device__ float    g_Q  [BB * NN * DD];
__device__ float    g_K  [BB * NN * DD];
__device__ float    g_V  [BB * NN * DD];
__device__ float    g_att[BB * NN * DD];
__device__ int      g_rowptr[NN + 1];
__device__ int2     g_edge[ETOT];          // (src, norm-as-int)
__device__ uint32_t g_bmask[NN * 16];      // packed mask bits
__device__ float    g_A[NN * NN];          // dense normalized adjacency

// ---------------- helpers -----------------------------------------------------
__device__ __forceinline__ uint32_t f2tf32(float f) {
    uint32_t r;
    asm("cvt.rna.tf32.f32 %0, %1;" : "=r"(r) : "f"(f));
    return r;
}
__device__ __forceinline__ void mma_tf32(float* c, const uint32_t* a,
                                         uint32_t b0, uint32_t b1) {
    asm volatile(
        "mma.sync.aligned.m16n8k8.row.col.f32.tf32.tf32.f32 "
        "{%0,%1,%2,%3}, {%4,%5,%6,%7}, {%8,%9}, {%0,%1,%2,%3};"
        : "+f"(c[0]), "+f"(c[1]), "+f"(c[2]), "+f"(c[3])
        : "r"(a[0]), "r"(a[1]), "r"(a[2]), "r"(a[3]), "r"(b0), "r"(b1));
}

// ---------------- fused single-CTA graph prep + dense A + mask pack -----------
__global__ __launch_bounds__(NN) void k_graph(const int* __restrict__ edge,
                                              const int* __restrict__ mask) {
    __shared__ int sdeg[NN];
    __shared__ int scnt[NN];
    __shared__ int srow[NN];
    __shared__ int ss[NN];
    __shared__ int se64;
    int t = threadIdx.x;

    if (t == 0) {
        int nz = 0;
        for (int i = 0; i < 64; i++) nz += (edge[2 * i + 1] != 0);
        se64 = (nz == 0) ? 1 : 0;
    }
    sdeg[t] = 0;
    scnt[t] = 0;
    __syncthreads();
    int e64 = se64;

    for (int e = t; e < ETOT; e += NN) {
        int dst = (e < EE) ? (e64 ? edge[2 * (EE + e)] : edge[EE + e]) : (e - EE);
        if (dst >= 0 && dst < NN) atomicAdd(&sdeg[dst], 1);
    }
    __syncthreads();

    ss[t] = sdeg[t];
    __syncthreads();
    for (int off = 1; off < NN; off <<= 1) {
        int v = (t >= off) ? ss[t - off] : 0;
        __syncthreads();
        ss[t] += v;
        __syncthreads();
    }
    srow[t] = ss[t] - sdeg[t];
    g_rowptr[t + 1] = ss[t];
    if (t == 0) g_rowptr[0] = 0;
    __syncthreads();

    for (int e = t; e < ETOT; e += NN) {
        int s, d;
        if (e < EE) {
            s = e64 ? edge[2 * e] : edge[e];
            d = e64 ? edge[2 * (EE + e)] : edge[EE + e];
        } else {
            s = e - EE; d = e - EE;
        }
        if (s < 0 || s >= NN || d < 0 || d >= NN) continue;
        float nm = rsqrtf((float)sdeg[s]) * rsqrtf((float)sdeg[d]);
        int pos = srow[d] + atomicAdd(&scnt[d], 1);
        g_edge[pos] = make_int2(s, __float_as_int(nm));
    }
    __syncthreads();

    // dense A row t (deterministic serial fill, duplicates accumulate)
    float4* arow4 = (float4*)(g_A + (size_t)t * NN);
    #pragma unroll 8
    for (int i = 0; i < NN / 4; i++) arow4[i] = make_float4(0.f, 0.f, 0.f, 0.f);
    float* arow = g_A + (size_t)t * NN;
    for (int i = srow[t]; i < ss[t]; i++) {
        int2 e = g_edge[i];
        arow[e.x] += __int_as_float(e.y);
    }

    // mask bit-packing (independent of graph data)
    for (int i = t; i < NN * 16; i += NN) {
        int r  = i >> 4;
        int wd = i & 15;
        const int* mrow = mask + (size_t)r * NN + wd * 32;
        uint32_t bits = 0;
        #pragma unroll
        for (int j = 0; j < 32; j++) bits |= (mrow[j] ? 1u : 0u) << j;
        g_bmask[i] = bits;
    }
}

// ---------------- tf32 mma.sync GEMM, CTA 128x256, warp tile 64x64 ------------
#define ASTRIDE 36
#define BSTRIDE 260
#define GS_SMEM ((128 * ASTRIDE + 32 * BSTRIDE + 256) * 4)

__global__ __launch_bounds__(256) void k_gemm_mma(
    const float* __restrict__ a0p, const float* __restrict__ a1p,
    const float* __restrict__ a2p,
    const float* __restrict__ w0, const float* __restrict__ w1,
    const float* __restrict__ w2,
    float* __restrict__ c0p, float* __restrict__ c1p, float* __restrict__ c2p,
    const float* __restrict__ bias)
{
    extern __shared__ uint32_t dyn[];
    uint32_t* As  = dyn;                       // 128 x ASTRIDE
    uint32_t* Bs  = As + 128 * ASTRIDE;        // 32 x BSTRIDE
    float*    bsh = (float*)(Bs + 32 * BSTRIDE);

    const int z = blockIdx.y;
    const float* A  = (z == 0) ? a0p : (z == 1) ? a1p : a2p;
    const float* Wm = (z == 0) ? w0  : (z == 1) ? w1  : w2;
    float*       C  = (z == 0) ? c0p : (z == 1) ? c1p : c2p;

    const int m0 = blockIdx.x * 128;

    int tid  = threadIdx.x;
    int wid  = tid >> 5;
    int lane = tid & 31;
    int grp  = lane >> 2;
    int tig  = lane & 3;
    int wm   = (wid & 1) * 64;
    int wn   = (wid >> 1) * 64;

    bsh[tid] = bias ? bias[tid] : 0.f;

    float acc[4][8][4];
    #pragma unroll
    for (int i = 0; i < 4; i++)
        #pragma unroll
        for (int j = 0; j < 8; j++)
            #pragma unroll
            for (int r = 0; r < 4; r++) acc[i][j][r] = 0.f;

    for (int k0 = 0; k0 < 256; k0 += 32) {
        #pragma unroll
        for (int t = 0; t < 4; t++) {
            int i   = tid + t * 256;
            int row = i >> 3;
            int q   = (i & 7) * 4;
            float4 v = *(const float4*)(A + (size_t)(m0 + row) * 256 + k0 + q);
            uint4 u;
            u.x = f2tf32(v.x); u.y = f2tf32(v.y);
            u.z = f2tf32(v.z); u.w = f2tf32(v.w);
            *(uint4*)(As + row * ASTRIDE + q) = u;
        }
        #pragma unroll
        for (int t = 0; t < 8; t++) {
            int i = tid + t * 256;
            int k = i >> 6;
            int q = (i & 63) * 4;
            float4 v = *(const float4*)(Wm + (size_t)(k0 + k) * 256 + q);
            uint4 u;
            u.x = f2tf32(v.x); u.y = f2tf32(v.y);
            u.z = f2tf32(v.z); u.w = f2tf32(v.w);
            *(uint4*)(Bs + k * BSTRIDE + q) = u;
        }
        __syncthreads();

        #pragma unroll
        for (int ks = 0; ks < 4; ks++) {
            int kk = ks * 8;
            uint32_t af[4][4], bf[8][2];
            #pragma unroll
            for (int mt = 0; mt < 4; mt++) {
                int r = wm + mt * 16 + grp;
                af[mt][0] = As[r * ASTRIDE + kk + tig];
                af[mt][1] = As[(r + 8) * ASTRIDE + kk + tig];
                af[mt][2] = As[r * ASTRIDE + kk + tig + 4];
                af[mt][3] = As[(r + 8) * ASTRIDE + kk + tig + 4];
            }
            #pragma unroll
            for (int nt = 0; nt < 8; nt++) {
                int c = wn + nt * 8 + grp;
                bf[nt][0] = Bs[(kk + tig) * BSTRIDE + c];
                bf[nt][1] = Bs[(kk + tig + 4) * BSTRIDE + c];
            }
            #pragma unroll
            for (int mt = 0; mt < 4; mt++)
                #pragma unroll
                for (int nt = 0; nt < 8; nt++)
                    mma_tf32(acc[mt][nt], af[mt], bf[nt][0], bf[nt][1]);
        }
        __syncthreads();
    }

    #pragma unroll
    for (int mt = 0; mt < 4; mt++) {
        #pragma unroll
        for (int nt = 0; nt < 8; nt++) {
            int cc = wn + nt * 8 + tig * 2;
            float b0 = bsh[cc], b1 = bsh[cc + 1];
            size_t r0 = (size_t)(m0 + wm + mt * 16 + grp) * 256 + cc;
            size_t r1 = r0 + 8 * 256;
            float2 v0 = {acc[mt][nt][0] + b0, acc[mt][nt][1] + b1};
            float2 v1 = {acc[mt][nt][2] + b0, acc[mt][nt][3] + b1};
            *(float2*)(C + r0) = v0;
            *(float2*)(C + r1) = v1;
        }
    }
}

// ---------------- aggregation GEMM: out[z][b] = A @ xw[z][b]  (K=512) ---------
__global__ __launch_bounds__(256) void k_agg_gemm(
    const float* __restrict__ xq, const float* __restrict__ xk,
    const float* __restrict__ xv,
    const float* __restrict__ bq, const float* __restrict__ bk,
    const float* __restrict__ bv,
    float* __restrict__ oq, float* __restrict__ ok_, float* __restrict__ ov)
{
    extern __shared__ uint32_t dyn[];
    uint32_t* As  = dyn;
    uint32_t* Bs  = As + 128 * ASTRIDE;
    float*    bsh = (float*)(Bs + 32 * BSTRIDE);

    int zz = blockIdx.y;
    int z  = zz >> 5;
    int b  = zz & 31;
    const float* X    = (z == 0) ? xq : (z == 1) ? xk : xv;
    const float* bias = (z == 0) ? bq : (z == 1) ? bk : bv;
    float*       O    = (z == 0) ? oq : (z == 1) ? ok_ : ov;
    const float* Xb = X + (size_t)b * NN * DD;
    float*       Cb = O + (size_t)b * NN * DD;

    const int m0 = blockIdx.x * 128;

    int tid  = threadIdx.x;
    int wid  = tid >> 5;
    int lane = tid & 31;
    int grp  = lane >> 2;
    int tig  = lane & 3;
    int wm   = (wid & 1) * 64;
    int wn   = (wid >> 1) * 64;

    bsh[tid] = bias[tid];

    float acc[4][8][4];
    #pragma unroll
    for (int i = 0; i < 4; i++)
        #pragma unroll
        for (int j = 0; j < 8; j++)
            #pragma unroll
            for (int r = 0; r < 4; r++) acc[i][j][r] = 0.f;

    for (int k0 = 0; k0 < NN; k0 += 32) {
        #pragma unroll
        for (int t = 0; t < 4; t++) {
            int i   = tid + t * 256;
            int row = i >> 3;
            int q   = (i & 7) * 4;
            float4 v = *(const float4*)(g_A + (size_t)(m0 + row) * NN + k0 + q);
            uint4 u;
            u.x = f2tf32(v.x); u.y = f2tf32(v.y);
            u.z = f2tf32(v.z); u.w = f2tf32(v.w);
            *(uint4*)(As + row * ASTRIDE + q) = u;
        }
        #pragma unroll
        for (int t = 0; t < 8; t++) {
            int i = tid + t * 256;
            int k = i >> 6;
            int q = (i & 63) * 4;
            float4 v = *(const float4*)(Xb + (size_t)(k0 + k) * 256 + q);
            uint4 u;
            u.x = f2tf32(v.x); u.y = f2tf32(v.y);
            u.z = f2tf32(v.z); u.w = f2tf32(v.w);
            *(uint4*)(Bs + k * BSTRIDE + q) = u;
        }
        __syncthreads();

        #pragma unroll
        for (int ks = 0; ks < 4; ks++) {
            int kk = ks * 8;
            uint32_t af[4][4], bf[8][2];
            #pragma unroll
            for (int mt = 0; mt < 4; mt++) {
                int r = wm + mt * 16 + grp;
                af[mt][0] = As[r * ASTRIDE + kk + tig];
                af[mt][1] = As[(r + 8) * ASTRIDE + kk + tig];
                af[mt][2] = As[r * ASTRIDE + kk + tig + 4];
                af[mt][3] = As[(r + 8) * ASTRIDE + kk + tig + 4];
            }
            #pragma unroll
            for (int nt = 0; nt < 8; nt++) {
                int c = wn + nt * 8 + grp;
                bf[nt][0] = Bs[(kk + tig) * BSTRIDE + c];
                bf[nt][1] = Bs[(kk + tig + 4) * BSTRIDE + c];
            }
            #pragma unroll
            for (int mt = 0; mt < 4; mt++)
                #pragma unroll
                for (int nt = 0; nt < 8; nt++)
                    mma_tf32(acc[mt][nt], af[mt], bf[nt][0], bf[nt][1]);
        }
        __syncthreads();
    }

    #pragma unroll
    for (int mt = 0; mt < 4; mt++) {
        #pragma unroll
        for (int nt = 0; nt < 8; nt++) {
            int cc = wn + nt * 8 + tig * 2;
            float b0 = bsh[cc], b1 = bsh[cc + 1];
            size_t r0 = (size_t)(m0 + wm + mt * 16 + grp) * 256 + cc;
            size_t r1 = r0 + 8 * 256;
            float2 v0 = {acc[mt][nt][0] + b0, acc[mt][nt][1] + b1};
            float2 v1 = {acc[mt][nt][2] + b0, acc[mt][nt][3] + b1};
            *(float2*)(Cb + r0) = v0;
            *(float2*)(Cb + r1) = v1;
        }
    }
}

// ---------------- flash attention, 32 q-rows per warp -------------------------
#define KV_ST 36
#define P_ST  68
#define ATT_SMEM ((64 * KV_ST * 2 + 8 * 32 * P_ST) * 4)

__global__ __launch_bounds__(256) void k_attn(
    const float* __restrict__ Q, const float* __restrict__ K,
    const float* __restrict__ V, float* __restrict__ out)
{
    extern __shared__ float sm[];
    uint32_t* Ks = (uint32_t*)sm;
    uint32_t* Vs = Ks + 64 * KV_ST;
    uint32_t* Ps = Vs + 64 * KV_ST;            // 8 warps x 32 x P_ST

    int h   = blockIdx.y;
    int b   = blockIdx.z;
    int tid = threadIdx.x;
    int wid = tid >> 5, lane = tid & 31;
    int grp = lane >> 2, tig = lane & 3;
    int qw  = blockIdx.x * 256 + wid * 32;
    uint32_t* Pw = Ps + wid * 32 * P_ST;

    const float* Qb = Q + (size_t)b * NN * DD + h * HDIM;
    const float* Kb = K + (size_t)b * NN * DD + h * HDIM;
    const float* Vb = V + (size_t)b * NN * DD + h * HDIM;

    const float escale = 0.17677669529663687f;

    uint32_t qa[2][4][4];
    #pragma unroll
    for (int mf = 0; mf < 2; mf++)
        #pragma unroll
        for (int kf = 0; kf < 4; kf++) {
            int cl = kf * 8 + tig;
            int r  = qw + mf * 16 + grp;
            qa[mf][kf][0] = f2tf32(Qb[(size_t)r * DD + cl] * escale);
            qa[mf][kf][1] = f2tf32(Qb[(size_t)(r + 8) * DD + cl] * escale);
            qa[mf][kf][2] = f2tf32(Qb[(size_t)r * DD + cl + 4] * escale);
            qa[mf][kf][3] = f2tf32(Qb[(size_t)(r + 8) * DD + cl + 4] * escale);
        }

    float mx[2][2], lx[2][2];
    #pragma unroll
    for (int mf = 0; mf < 2; mf++) {
        mx[mf][0] = -3.4e38f; mx[mf][1] = -3.4e38f;
        lx[mf][0] = 0.f;      lx[mf][1] = 0.f;
    }
    float oacc[2][4][4];
    #pragma unroll
    for (int mf = 0; mf < 2; mf++)
        #pragma unroll
        for (int nt = 0; nt < 4; nt++)
            #pragma unroll
            for (int r = 0; r < 4; r++) oacc[mf][nt][r] = 0.f;

    for (int c0 = 0; c0 < NN; c0 += 64) {
        __syncthreads();
        #pragma unroll
        for (int t = 0; t < 2; t++) {
            int i = tid + t * 256;
            int r = i >> 3, f = (i & 7) * 4;
            float4 kv = *(const float4*)(Kb + (size_t)(c0 + r) * DD + f);
            float4 vv = *(const float4*)(Vb + (size_t)(c0 + r) * DD + f);
            uint4 ku, vu;
            ku.x = f2tf32(kv.x); ku.y = f2tf32(kv.y);
            ku.z = f2tf32(kv.z); ku.w = f2tf32(kv.w);
            vu.x = f2tf32(vv.x); vu.y = f2tf32(vv.y);
            vu.z = f2tf32(vv.z); vu.w = f2tf32(vv.w);
            *(uint4*)(Ks + r * KV_ST + f) = ku;
            *(uint4*)(Vs + r * KV_ST + f) = vu;
        }
        __syncthreads();

        #pragma unroll
        for (int mf = 0; mf < 2; mf++) {
            float sacc[8][4];
            #pragma unroll
            for (int nt = 0; nt < 8; nt++)
                #pragma unroll
                for (int r = 0; r < 4; r++) sacc[nt][r] = 0.f;
            #pragma unroll
            for (int nt = 0; nt < 8; nt++)
                #pragma unroll
                for (int kf = 0; kf < 4; kf++) {
                    uint32_t b0v = Ks[(nt * 8 + grp) * KV_ST + kf * 8 + tig];
                    uint32_t b1v = Ks[(nt * 8 + grp) * KV_ST + kf * 8 + tig + 4];
                    mma_tf32(sacc[nt], qa[mf][kf], b0v, b1v);
                }

            int r0 = qw + mf * 16 + grp;
            uint32_t wa0 = g_bmask[r0 * 16 + (c0 >> 5)];
            uint32_t wa1 = g_bmask[r0 * 16 + (c0 >> 5) + 1];
            uint32_t wb0 = g_bmask[(r0 + 8) * 16 + (c0 >> 5)];
            uint32_t wb1 = g_bmask[(r0 + 8) * 16 + (c0 >> 5) + 1];
            float cm0 = -3.4e38f, cm1 = -3.4e38f;
            #pragma unroll
            for (int nt = 0; nt < 8; nt++) {
                int j  = nt * 8 + 2 * tig;
                uint32_t wa = (j < 32) ? wa0 : wa1;
                uint32_t wb = (j < 32) ? wb0 : wb1;
                int sh = j & 31;
                if (!((wa >> sh) & 1))        sacc[nt][0] = -1e10f;
                if (!((wa >> (sh + 1)) & 1))  sacc[nt][1] = -1e10f;
                if (!((wb >> sh) & 1))        sacc[nt][2] = -1e10f;
                if (!((wb >> (sh + 1)) & 1))  sacc[nt][3] = -1e10f;
                cm0 = fmaxf(cm0, fmaxf(sacc[nt][0], sacc[nt][1]));
                cm1 = fmaxf(cm1, fmaxf(sacc[nt][2], sacc[nt][3]));
            }
            cm0 = fmaxf(cm0, __shfl_xor_sync(0xffffffffu, cm0, 1));
            cm0 = fmaxf(cm0, __shfl_xor_sync(0xffffffffu, cm0, 2));
            cm1 = fmaxf(cm1, __shfl_xor_sync(0xffffffffu, cm1, 1));
            cm1 = fmaxf(cm1, __shfl_xor_sync(0xffffffffu, cm1, 2));

            float nm0 = fmaxf(mx[mf][0], cm0), nm1 = fmaxf(mx[mf][1], cm1);
            float f0 = __expf(mx[mf][0] - nm0), f1 = __expf(mx[mf][1] - nm1);
            lx[mf][0] *= f0; lx[mf][1] *= f1;
            #pragma unroll
            for (int nt = 0; nt < 4; nt++) {
                oacc[mf][nt][0] *= f0; oacc[mf][nt][1] *= f0;
                oacc[mf][nt][2] *= f1; oacc[mf][nt][3] *= f1;
            }
            mx[mf][0] = nm0; mx[mf][1] = nm1;

            #pragma unroll
            for (int nt = 0; nt < 8; nt++) {
                float p0 = __expf(sacc[nt][0] - nm0);
                float p1 = __expf(sacc[nt][1] - nm0);
                float p2 = __expf(sacc[nt][2] - nm1);
                float p3 = __expf(sacc[nt][3] - nm1);
                lx[mf][0] += p0 + p1; lx[mf][1] += p2 + p3;
                uint2 u0, u1;
                u0.x = f2tf32(p0); u0.y = f2tf32(p1);
                u1.x = f2tf32(p2); u1.y = f2tf32(p3);
                *(uint2*)(Pw + (mf * 16 + grp) * P_ST + nt * 8 + 2 * tig) = u0;
                *(uint2*)(Pw + (mf * 16 + grp + 8) * P_ST + nt * 8 + 2 * tig) = u1;
            }
        }
        __syncwarp();

        #pragma unroll
        for (int kb = 0; kb < 8; kb++) {
            uint32_t vb[4][2];
            #pragma unroll
            for (int nt = 0; nt < 4; nt++) {
                vb[nt][0] = Vs[(kb * 8 + tig) * KV_ST + nt * 8 + grp];
                vb[nt][1] = Vs[(kb * 8 + tig + 4) * KV_ST + nt * 8 + grp];
            }
            #pragma unroll
            for (int mf = 0; mf < 2; mf++) {
                uint32_t pa[4];
                pa[0] = Pw[(mf * 16 + grp) * P_ST + kb * 8 + tig];
                pa[1] = Pw[(mf * 16 + grp + 8) * P_ST + kb * 8 + tig];
                pa[2] = Pw[(mf * 16 + grp) * P_ST + kb * 8 + tig + 4];
                pa[3] = Pw[(mf * 16 + grp + 8) * P_ST + kb * 8 + tig + 4];
                #pragma unroll
                for (int nt = 0; nt < 4; nt++)
                    mma_tf32(oacc[mf][nt], pa, vb[nt][0], vb[nt][1]);
            }
        }
        __syncwarp();
    }

    #pragma unroll
    for (int mf = 0; mf < 2; mf++) {
        float l0 = lx[mf][0], l1 = lx[mf][1];
        l0 += __shfl_xor_sync(0xffffffffu, l0, 1);
        l0 += __shfl_xor_sync(0xffffffffu, l0, 2);
        l1 += __shfl_xor_sync(0xffffffffu, l1, 1);
        l1 += __shfl_xor_sync(0xffffffffu, l1, 2);
        float inv0 = 1.f / l0, inv1 = 1.f / l1;

        int r = qw + mf * 16 + grp;
        float* o0 = out + ((size_t)b * NN + r) * DD + h * HDIM;
        float* o1 = out + ((size_t)b * NN + r + 8) * DD + h * HDIM;
        #pragma unroll
        for (int nt = 0; nt < 4; nt++) {
            int cl = nt * 8 + 2 * tig;
            float2 v0 = {oacc[mf][nt][0] * inv0, oacc[mf][nt][1] * inv0};
            float2 v1 = {oacc[mf][nt][2] * inv1, oacc[mf][nt][3] * inv1};
            *(float2*)(o0 + cl) = v0;
            *(float2*)(o1 + cl) = v1;
        }
    }
}

// ---------------- launch ------------------------------------------------------
extern "C" void kernel_launch(void* const* d_in, const int* in_sizes, int n_in,
                              void* d_out, int out_size) {
    const float* query = (const float*)d_in[0];
    const float* key   = (const float*)d_in[1];
    const float* value = (const float*)d_in[2];
    const int*   edge  = (const int*)d_in[3];
    const int*   mask  = (const int*)d_in[4];
    const float* Wq = (const float*)d_in[5];
    const float* bq = (const float*)d_in[6];
    const float* Wk = (const float*)d_in[7];
    const float* bk = (const float*)d_in[8];
    const float* Wv = (const float*)d_in[9];
    const float* bv = (const float*)d_in[10];
    const float* Wo = (const float*)d_in[11];
    const float* bo = (const float*)d_in[12];
    float* out = (float*)d_out;

    float *xwq, *xwk, *xwv, *Qp, *Kp, *Vp, *att;
    cudaGetSymbolAddress((void**)&xwq, g_xwq);
    cudaGetSymbolAddress((void**)&xwk, g_xwk);
    cudaGetSymbolAddress((void**)&xwv, g_xwv);
    cudaGetSymbolAddress((void**)&Qp,  g_Q);
    cudaGetSymbolAddress((void**)&Kp,  g_K);
    cudaGetSymbolAddress((void**)&Vp,  g_V);
    cudaGetSymbolAddress((void**)&att, g_att);

    cudaFuncSetAttribute(k_attn, cudaFuncAttributeMaxDynamicSharedMemorySize,
                         ATT_SMEM);
    cudaFuncSetAttribute(k_gemm_mma, cudaFuncAttributeMaxDynamicSharedMemorySize,
                         GS_SMEM);
    cudaFuncSetAttribute(k_agg_gemm, cudaFuncAttributeMaxDynamicSharedMemorySize,
                         GS_SMEM);

    // 1: graph prep + dense adjacency + mask packing
    k_graph<<<1, NN>>>(edge, mask);

    // 2: fused QKV projection
    k_gemm_mma<<<dim3(128, 3), 256, GS_SMEM>>>(query, key, value,
                                               Wq, Wk, Wv,
                                               xwq, xwk, xwv, nullptr);

    // 3: aggregation GEMM (+bias)
    k_agg_gemm<<<dim3(4, 96), 256, GS_SMEM>>>(xwq, xwk, xwv,
                                              bq, bk, bv, Qp, Kp, Vp);

    // 4: flash attention  (<- ncu capture slot)
    k_attn<<<dim3(2, HH, BB), 256, ATT_SMEM>>>(Qp, Kp, Vp, att);

    // 5: output projection (+bias) into d_out
    k_gemm_mma<<<dim3(128, 1), 256, GS_SMEM>>>(att, att, att,
                                               Wo, Wo, Wo,
                                               out, out, out, bo);
}